// round 1
// baseline (speedup 1.0000x reference)
#include <cuda_runtime.h>
#include <math.h>

// Problem constants (fixed by setup_inputs)
#define N_NODES 1024
#define N_EDGES 16384
#define D_IN    128
#define ED      16
#define KTOP    8
#define NEG_INF -1000000000.0f

// ---------------- scratch (device globals; no allocations allowed) ----------
__device__ int   g_minEdge[N_NODES * N_NODES];   // first edge id per (src,dst), sentinel INT_MAX
__device__ int   g_maxEdge[N_NODES * N_NODES];   // last  edge id per (src,dst), sentinel -1
__device__ float g_xwnode[N_NODES];              // x @ w_node + b
__device__ float g_xwnb[N_NODES];                // x @ w_nb
__device__ float g_eval[N_EDGES];                // edge_attr @ w_e
__device__ int   g_topi[N_NODES * KTOP];         // selected dst per (node, k)
__device__ int   g_eid[N_NODES * KTOP];          // matched original edge id (or 0)
__device__ float g_m[N_NODES * KTOP * D_IN];     // per-edge message
__device__ float g_mx[N_NODES * D_IN];           // segment max
__device__ float g_den[N_NODES * D_IN];          // segment sum w
__device__ float g_num[N_NODES * D_IN];          // segment sum w*m
__device__ float g_h1[N_NODES * 64];             // conv1 output (post-relu)
__device__ float g_h2[N_NODES * 64];             // conv2 output (post-relu)

// ---------------- kernels ----------------------------------------------------

__global__ void init_maps() {
    int idx = blockIdx.x * blockDim.x + threadIdx.x;
    const int total = N_NODES * N_NODES;
    const int stride = gridDim.x * blockDim.x;
    for (; idx < total; idx += stride) {
        g_minEdge[idx] = 0x7fffffff;
        g_maxEdge[idx] = -1;
    }
}

__global__ void build_edges(const int* __restrict__ ei) {
    int e = blockIdx.x * blockDim.x + threadIdx.x;
    if (e >= N_EDGES) return;
    int s = ei[e];
    int d = ei[N_EDGES + e];
    int idx = s * N_NODES + d;
    atomicMin(&g_minEdge[idx], e);   // first match (argmax of boolean eq)
    atomicMax(&g_maxEdge[idx], e);   // last write wins (.set with duplicates)
}

// per-node dot products: xwnode = x[i].w_node + b, xwnb = x[i].w_nb
__global__ void node_dots(const float* __restrict__ x,
                          const float* __restrict__ mlp_w,
                          const float* __restrict__ mlp_b) {
    int i = blockIdx.x;
    int t = threadIdx.x;  // 128
    __shared__ float s1[128];
    __shared__ float s2[128];
    float xv = x[i * D_IN + t];
    s1[t] = xv * mlp_w[t];
    s2[t] = xv * mlp_w[D_IN + t];
    __syncthreads();
    for (int ofs = 64; ofs > 0; ofs >>= 1) {
        if (t < ofs) { s1[t] += s1[t + ofs]; s2[t] += s2[t + ofs]; }
        __syncthreads();
    }
    if (t == 0) {
        g_xwnode[i] = s1[0] + mlp_b[0];
        g_xwnb[i]   = s2[0];
    }
}

// per-edge scalar: edge_attr[e] . w_e
__global__ void edge_vals(const float* __restrict__ edge_attr,
                          const float* __restrict__ mlp_w) {
    int e = blockIdx.x * blockDim.x + threadIdx.x;
    if (e >= N_EDGES) return;
    float acc = 0.f;
#pragma unroll
    for (int c = 0; c < ED; c++) acc += edge_attr[e * ED + c] * mlp_w[2 * D_IN + c];
    g_eval[e] = acc;
}

// one block per row: score -> softmax z -> z + gumbel -> top-8 (ties: lowest idx)
__global__ void row_topk(const float* __restrict__ gumbel) {
    const int NT = 256;
    int i = blockIdx.x;
    int t = threadIdx.x;
    __shared__ float sval[N_NODES];
    __shared__ float rv[NT];
    __shared__ int   ri[NT];

    float xi = g_xwnode[i];

    // pass 1: scores + local max
    float lmax = -3.4e38f;
    for (int j = t; j < N_NODES; j += NT) {
        int me = g_maxEdge[i * N_NODES + j];
        float s = (me >= 0) ? (xi + g_xwnb[j] + g_eval[me]) : NEG_INF;
        sval[j] = s;
        lmax = fmaxf(lmax, s);
    }
    rv[t] = lmax;
    __syncthreads();
    for (int ofs = NT / 2; ofs > 0; ofs >>= 1) {
        if (t < ofs) rv[t] = fmaxf(rv[t], rv[t + ofs]);
        __syncthreads();
    }
    float smax = rv[0];
    __syncthreads();

    // pass 2: exp + sum
    float lsum = 0.f;
    for (int j = t; j < N_NODES; j += NT) {
        float e = expf(sval[j] - smax);
        sval[j] = e;
        lsum += e;
    }
    rv[t] = lsum;
    __syncthreads();
    for (int ofs = NT / 2; ofs > 0; ofs >>= 1) {
        if (t < ofs) rv[t] += rv[t + ofs];
        __syncthreads();
    }
    float inv = 1.f / rv[0];
    __syncthreads();

    // pass 3: val = z + gumbel
    for (int j = t; j < N_NODES; j += NT) {
        float u = gumbel[i * N_NODES + j];
        float gg = -logf(-logf(u + 1e-20f) + 1e-20f);
        sval[j] = sval[j] * inv + gg;
    }
    __syncthreads();

    // top-8 by iterative argmax (tie -> lowest index, matching jax.lax.top_k)
    for (int r = 0; r < KTOP; r++) {
        float bv = -3.4e38f;
        int   bi = N_NODES;
        for (int j = t; j < N_NODES; j += NT) {
            float v = sval[j];
            if (v > bv || (v == bv && j < bi)) { bv = v; bi = j; }
        }
        rv[t] = bv; ri[t] = bi;
        __syncthreads();
        for (int ofs = NT / 2; ofs > 0; ofs >>= 1) {
            if (t < ofs) {
                float v2 = rv[t + ofs]; int i2 = ri[t + ofs];
                if (v2 > rv[t] || (v2 == rv[t] && i2 < ri[t])) { rv[t] = v2; ri[t] = i2; }
            }
            __syncthreads();
        }
        if (t == 0) {
            int win = ri[0];
            g_topi[i * KTOP + r] = win;
            int me = g_minEdge[i * N_NODES + win];
            g_eid[i * KTOP + r] = (me < N_EDGES) ? me : 0;  // no match -> edge 0
            sval[win] = -3.4e38f;
        }
        __syncthreads();
    }
}

__global__ void zero_nodebufs(int din) {
    int idx = blockIdx.x * blockDim.x + threadIdx.x;
    int total = N_NODES * din;
    int stride = gridDim.x * blockDim.x;
    for (; idx < total; idx += stride) {
        g_mx[idx] = 0.f;
        g_den[idx] = 0.f;
        g_num[idx] = 0.f;
    }
}

// per-edge message m = relu(xn[src] + attr@We + be) + eps; segment max via int atomicMax (m>0)
template <int DIN, bool USE_H1>
__global__ void edge_msg(const float* __restrict__ xn,
                         const float* __restrict__ edge_attr,
                         const float* __restrict__ We,
                         const float* __restrict__ be) {
    int k = blockIdx.x;     // 8192 edges
    int f = threadIdx.x;    // DIN
    __shared__ float a[ED];
    int e = g_eid[k];
    if (f < ED) a[f] = edge_attr[e * ED + f];
    __syncthreads();
    int src = k >> 3;
    int dst = g_topi[k];
    const float* xsrc = USE_H1 ? (g_h1 + src * DIN) : (xn + src * DIN);
    float ep = be[f];
#pragma unroll
    for (int c = 0; c < ED; c++) ep += a[c] * We[c * DIN + f];
    float mv = fmaxf(xsrc[f] + ep, 0.f) + 1e-7f;
    g_m[k * DIN + f] = mv;
    atomicMax((int*)&g_mx[dst * DIN + f], __float_as_int(mv));  // mv > 0 -> int-order == float-order
}

// per-edge softmax-weight aggregation
template <int DIN>
__global__ void edge_agg() {
    int k = blockIdx.x;
    int f = threadIdx.x;
    int dst = g_topi[k];
    float mv = g_m[k * DIN + f];
    float w = expf(mv - g_mx[dst * DIN + f]);
    atomicAdd(&g_den[dst * DIN + f], w);
    atomicAdd(&g_num[dst * DIN + f], w * mv);
}

// per-node: out0 = agg + xn; h1 = relu(out0 @ W1 + b1); out = relu(h1 @ W2 + b2)
template <int DIN, int DH, int DOUT, bool USE_H1>
__global__ void node_mlp(const float* __restrict__ xn,
                         const float* __restrict__ W1, const float* __restrict__ b1,
                         const float* __restrict__ W2, const float* __restrict__ b2) {
    int i = blockIdx.x;
    int t = threadIdx.x;  // DH threads
    __shared__ float s0[DIN];
    __shared__ float h1s[DH];
    if (t < DIN) {
        float d = g_den[i * DIN + t];
        float a = (d > 0.f) ? (g_num[i * DIN + t] / d) : 0.f;
        const float* xsrc = USE_H1 ? (g_h1 + i * DIN) : (xn + i * DIN);
        s0[t] = a + xsrc[t];
    }
    __syncthreads();
    float acc = b1[t];
#pragma unroll 8
    for (int c = 0; c < DIN; c++) acc += s0[c] * W1[c * DH + t];
    h1s[t] = fmaxf(acc, 0.f);
    __syncthreads();
    if (t < DOUT) {
        float acc2 = b2[t];
#pragma unroll 8
        for (int c = 0; c < DH; c++) acc2 += h1s[c] * W2[c * DOUT + t];
        float r = fmaxf(acc2, 0.f);  // post-genconv relu
        float* out = USE_H1 ? g_h2 : g_h1;
        out[i * DOUT + t] = r;
    }
}

__global__ void final_fc(const float* __restrict__ fc_w,
                         const float* __restrict__ fc_b,
                         const int* __restrict__ node_mask,
                         float* __restrict__ out) {
    int i = blockIdx.x;
    int t = threadIdx.x;  // 64
    __shared__ float sh[64];
    sh[t] = g_h2[i * 64 + t];
    __syncthreads();
    if (t < 40) {
        float acc = fc_b[t];
#pragma unroll
        for (int c = 0; c < 64; c++) acc += sh[c] * fc_w[c * 40 + t];
        out[i * 40 + t] = (node_mask[i] != 0) ? acc : 0.f;
    }
}

// ---------------- launch ------------------------------------------------------

extern "C" void kernel_launch(void* const* d_in, const int* in_sizes, int n_in,
                              void* d_out, int out_size) {
    const float* x         = (const float*)d_in[0];
    const float* edge_attr = (const float*)d_in[1];
    const float* gumbel    = (const float*)d_in[2];
    const float* mlp_w     = (const float*)d_in[3];
    const float* mlp_b     = (const float*)d_in[4];
    const float* c1_we = (const float*)d_in[5];
    const float* c1_be = (const float*)d_in[6];
    const float* c1_w1 = (const float*)d_in[7];
    const float* c1_b1 = (const float*)d_in[8];
    const float* c1_w2 = (const float*)d_in[9];
    const float* c1_b2 = (const float*)d_in[10];
    const float* c2_we = (const float*)d_in[11];
    const float* c2_be = (const float*)d_in[12];
    const float* c2_w1 = (const float*)d_in[13];
    const float* c2_b1 = (const float*)d_in[14];
    const float* c2_w2 = (const float*)d_in[15];
    const float* c2_b2 = (const float*)d_in[16];
    const float* fc_w  = (const float*)d_in[17];
    const float* fc_b  = (const float*)d_in[18];
    // d_in[19] = num_nodes (constant 1024, unused)
    const int* edge_index = (const int*)d_in[20];
    const int* node_mask  = (const int*)d_in[21];
    float* out = (float*)d_out;

    // graph construction maps
    init_maps<<<512, 256>>>();
    build_edges<<<(N_EDGES + 255) / 256, 256>>>(edge_index);

    // score precomputes
    node_dots<<<N_NODES, 128>>>(x, mlp_w, mlp_b);
    edge_vals<<<(N_EDGES + 255) / 256, 256>>>(edge_attr, mlp_w);

    // softmax + gumbel + top-8 + edge-id match
    row_topk<<<N_NODES, 256>>>(gumbel);

    // GENConv 1 (Din=128, hidden=256, out=64)
    zero_nodebufs<<<256, 256>>>(D_IN);
    edge_msg<D_IN, false><<<N_NODES * KTOP, D_IN>>>(x, edge_attr, c1_we, c1_be);
    edge_agg<D_IN><<<N_NODES * KTOP, D_IN>>>();
    node_mlp<D_IN, 256, 64, false><<<N_NODES, 256>>>(x, c1_w1, c1_b1, c1_w2, c1_b2);

    // GENConv 2 (Din=64, hidden=128, out=64)
    zero_nodebufs<<<256, 256>>>(64);
    edge_msg<64, true><<<N_NODES * KTOP, 64>>>(nullptr, edge_attr, c2_we, c2_be);
    edge_agg<64><<<N_NODES * KTOP, 64>>>();
    node_mlp<64, 128, 64, true><<<N_NODES, 128>>>(nullptr, c2_w1, c2_b1, c2_w2, c2_b2);

    // final fc + mask
    final_fc<<<N_NODES, 64>>>(fc_w, fc_b, node_mask, out);
}